// round 3
// baseline (speedup 1.0000x reference)
#include <cuda_runtime.h>
#include <cstdint>

#define NN 50000
#define EE 800000
#define CC 64
#define BN_EPS 1e-5f

typedef unsigned long long ull;

// ---------------- scratch (static __device__ globals; no allocation) ----------------
static __device__ __align__(16) float g_P[NN * CC];      // x @ W0[:64]
static __device__ __align__(16) float g_Q[NN * CC];      // x @ W0[64:]
static __device__ __align__(16) float g_Y[EE * CC];      // y1 scratch (pre-BN layer1 output)
static __device__ float g_cnt[NN];                       // dst degree (float)
static __device__ int   g_src[EE];
static __device__ int   g_dst[EE];
static __device__ __align__(16) float g_sum[3][CC];
static __device__ __align__(16) float g_sq[3][CC];
static __device__ __align__(16) float g_bnA[3][CC];      // g * rsqrt(var+eps)
static __device__ __align__(16) float g_bnB[3][CC];      // beta - mean*A
static __device__ int   g_is64;

// ---------------- f32x2 helpers (PTX-only on sm_103a) ----------------
__device__ __forceinline__ void fma2(ull& d, ull a, ull b) {
    asm("fma.rn.f32x2 %0, %1, %2, %0;" : "+l"(d) : "l"(a), "l"(b));
}
__device__ __forceinline__ ull pack2(float x) {
    ull r;
    asm("mov.b64 %0, {%1, %1};" : "=l"(r) : "f"(x));
    return r;
}
__device__ __forceinline__ float2 unpack2(ull v) {
    float2 u;
    asm("mov.b64 {%0, %1}, %2;" : "=f"(u.x), "=f"(u.y) : "l"(v));
    return u;
}

// ---------------- kernels ----------------

__global__ void k_zero(float* __restrict__ out_nodes) {
    int i = blockIdx.x * 256 + threadIdx.x;
    if (i < NN * CC) out_nodes[i] = 0.0f;
    if (i < NN) g_cnt[i] = 0.0f;
    if (i < 3 * CC) {
        ((float*)g_sum)[i] = 0.0f;
        ((float*)g_sq)[i] = 0.0f;
    }
}

// Detect whether edge_index is int64 (odd 32-bit words all zero) or int32.
__global__ void k_detect(const unsigned* __restrict__ w) {
    __shared__ int bad;
    if (threadIdx.x == 0) bad = 0;
    __syncthreads();
    int b = 0;
    for (int i = threadIdx.x; i < 1024; i += 256)
        if (w[2 * i + 1] != 0u) b = 1;
    if (b) atomicOr(&bad, 1);
    __syncthreads();
    if (threadIdx.x == 0) g_is64 = bad ? 0 : 1;
}

__global__ void k_convert(const void* __restrict__ ei) {
    int e = blockIdx.x * 256 + threadIdx.x;
    if (e >= EE) return;
    int s, d;
    if (g_is64) {
        const long long* p = (const long long*)ei;
        s = (int)p[e];
        d = (int)p[EE + e];
    } else {
        const int* p = (const int*)ei;
        s = p[e];
        d = p[EE + e];
    }
    g_src[e] = s;
    g_dst[e] = d;
}

// Node-level GEMM: P = x @ W0[:64], Q = x @ W0[64:].  Tile: 32 nodes x 128 cols per block.
__global__ void __launch_bounds__(256) k_node(const float* __restrict__ x,
                                              const float* __restrict__ W0) {
    __shared__ float sW[64][128];   // cols 0..63 = W0a, 64..127 = W0b
    __shared__ float sx[32][64];
    int t = threadIdx.x;
#pragma unroll
    for (int i = 0; i < 32; i++) {
        int idx = t + i * 256;      // 0..8191
        int k = idx >> 7;
        int cc = idx & 127;
        sW[k][cc] = (cc < 64) ? W0[k * 64 + cc] : W0[(64 + k) * 64 + (cc - 64)];
    }
    int n0 = blockIdx.x * 32;
#pragma unroll
    for (int i = 0; i < 8; i++) {
        int idx = t + i * 256;      // 0..2047
        int nl = idx >> 6;
        int k = idx & 63;
        int n = n0 + nl;
        sx[nl][k] = (n < NN) ? x[n * 64 + k] : 0.0f;
    }
    __syncthreads();
    int tc = t & 31;                // 4 cols each -> 128 cols
    int tn = t >> 5;                // 4 nodes each -> 32 nodes
    float acc[4][4] = {};
#pragma unroll 16
    for (int k = 0; k < 64; k++) {
        float4 w = *(const float4*)&sW[k][tc * 4];
        float x0 = sx[tn * 4 + 0][k];
        float x1 = sx[tn * 4 + 1][k];
        float x2 = sx[tn * 4 + 2][k];
        float x3 = sx[tn * 4 + 3][k];
        acc[0][0] = fmaf(x0, w.x, acc[0][0]); acc[0][1] = fmaf(x0, w.y, acc[0][1]);
        acc[0][2] = fmaf(x0, w.z, acc[0][2]); acc[0][3] = fmaf(x0, w.w, acc[0][3]);
        acc[1][0] = fmaf(x1, w.x, acc[1][0]); acc[1][1] = fmaf(x1, w.y, acc[1][1]);
        acc[1][2] = fmaf(x1, w.z, acc[1][2]); acc[1][3] = fmaf(x1, w.w, acc[1][3]);
        acc[2][0] = fmaf(x2, w.x, acc[2][0]); acc[2][1] = fmaf(x2, w.y, acc[2][1]);
        acc[2][2] = fmaf(x2, w.z, acc[2][2]); acc[2][3] = fmaf(x2, w.w, acc[2][3]);
        acc[3][0] = fmaf(x3, w.x, acc[3][0]); acc[3][1] = fmaf(x3, w.y, acc[3][1]);
        acc[3][2] = fmaf(x3, w.z, acc[3][2]); acc[3][3] = fmaf(x3, w.w, acc[3][3]);
    }
#pragma unroll
    for (int i = 0; i < 4; i++) {
        int n = n0 + tn * 4 + i;
        if (n < NN) {
            float4 v = make_float4(acc[i][0], acc[i][1], acc[i][2], acc[i][3]);
            if (tc < 16)
                *(float4*)&g_P[n * 64 + tc * 4] = v;
            else
                *(float4*)&g_Q[n * 64 + (tc - 16) * 4] = v;
        }
    }
}

// Layer-0 stats: per-column sum/sumsq of y0 = P[dst]+Q[src]; also dst degree counts.
__global__ void k_stats0() {
    __shared__ float ss[CC], sq[CC];
    int t = threadIdx.x;
    if (t < CC) { ss[t] = 0.0f; sq[t] = 0.0f; }
    __syncthreads();
    int lane = t & 31;
    int warp = (blockIdx.x * 256 + t) >> 5;
    int nw = (gridDim.x * 256) >> 5;
    float2 s = make_float2(0.0f, 0.0f), q = make_float2(0.0f, 0.0f);
    for (int e = warp; e < EE; e += nw) {
        int dst = g_dst[e], src = g_src[e];
        float2 p = *(const float2*)&g_P[dst * CC + 2 * lane];
        float2 qq = *(const float2*)&g_Q[src * CC + 2 * lane];
        float y0 = p.x + qq.x, y1 = p.y + qq.y;
        s.x += y0; s.y += y1;
        q.x = fmaf(y0, y0, q.x); q.y = fmaf(y1, y1, q.y);
        if (lane == 0) atomicAdd(&g_cnt[dst], 1.0f);
    }
    atomicAdd(&ss[2 * lane], s.x);
    atomicAdd(&ss[2 * lane + 1], s.y);
    atomicAdd(&sq[2 * lane], q.x);
    atomicAdd(&sq[2 * lane + 1], q.y);
    __syncthreads();
    if (t < CC) {
        atomicAdd(&g_sum[0][t], ss[t]);
        atomicAdd(&g_sq[0][t], sq[t]);
    }
}

__global__ void k_finalize(int layer, const float* __restrict__ gam,
                           const float* __restrict__ bet) {
    int c = threadIdx.x;
    float inv = 1.0f / (float)EE;
    float m = g_sum[layer][c] * inv;
    float v = g_sq[layer][c] * inv - m * m;
    float a = gam[c] * rsqrtf(v + BN_EPS);
    g_bnA[layer][c] = a;
    g_bnB[layer][c] = bet[c] - m * a;
}

// ---- shared GEMM core for the two edge layers ----
// Tile: 128 edges (64 f32x2 pairs) x 64 cols. 256 threads.
// te = t & 31 -> pair lanes; thread owns pairs {te, te+32}. tc = t >> 5 -> 8 cols.
// accs packed over edges -> fp32-exact.
__device__ __forceinline__ void gemm_core_store_stats(
    const float (*Ht)[128], const float (*Ws)[CC], int e0, int t,
    float* __restrict__ dstbuf, int layer_stats)
{
    int te = t & 31, tc = t >> 5;
    ull acc[2][8];
#pragma unroll
    for (int j = 0; j < 2; j++)
#pragma unroll
        for (int c = 0; c < 8; c++) acc[j][c] = 0ull;

#pragma unroll 8
    for (int k = 0; k < CC; k++) {
        ull h0 = *(const ull*)&Ht[k][te * 2];
        ull h1 = *(const ull*)&Ht[k][(te + 32) * 2];
        float4 wa = *(const float4*)&Ws[k][tc * 8];
        float4 wb = *(const float4*)&Ws[k][tc * 8 + 4];
        ull w0 = pack2(wa.x), w1 = pack2(wa.y), w2 = pack2(wa.z), w3 = pack2(wa.w);
        ull w4 = pack2(wb.x), w5 = pack2(wb.y), w6 = pack2(wb.z), w7 = pack2(wb.w);
        fma2(acc[0][0], h0, w0); fma2(acc[0][1], h0, w1);
        fma2(acc[0][2], h0, w2); fma2(acc[0][3], h0, w3);
        fma2(acc[0][4], h0, w4); fma2(acc[0][5], h0, w5);
        fma2(acc[0][6], h0, w6); fma2(acc[0][7], h0, w7);
        fma2(acc[1][0], h1, w0); fma2(acc[1][1], h1, w1);
        fma2(acc[1][2], h1, w2); fma2(acc[1][3], h1, w3);
        fma2(acc[1][4], h1, w4); fma2(acc[1][5], h1, w5);
        fma2(acc[1][6], h1, w6); fma2(acc[1][7], h1, w7);
    }

    float s[8], qs[8];
#pragma unroll
    for (int c = 0; c < 8; c++) { s[c] = 0.0f; qs[c] = 0.0f; }
#pragma unroll
    for (int j = 0; j < 2; j++) {
        int pj = te + 32 * j;
        int eA = e0 + pj * 2;
        float2 u[8];
#pragma unroll
        for (int c = 0; c < 8; c++) {
            u[c] = unpack2(acc[j][c]);
            s[c] += u[c].x + u[c].y;
            qs[c] = fmaf(u[c].x, u[c].x, fmaf(u[c].y, u[c].y, qs[c]));
        }
        *(float4*)&dstbuf[(size_t)eA * CC + tc * 8] =
            make_float4(u[0].x, u[1].x, u[2].x, u[3].x);
        *(float4*)&dstbuf[(size_t)eA * CC + tc * 8 + 4] =
            make_float4(u[4].x, u[5].x, u[6].x, u[7].x);
        *(float4*)&dstbuf[(size_t)(eA + 1) * CC + tc * 8] =
            make_float4(u[0].y, u[1].y, u[2].y, u[3].y);
        *(float4*)&dstbuf[(size_t)(eA + 1) * CC + tc * 8 + 4] =
            make_float4(u[4].y, u[5].y, u[6].y, u[7].y);
    }
#pragma unroll
    for (int off = 16; off > 0; off >>= 1)
#pragma unroll
        for (int c = 0; c < 8; c++) {
            s[c] += __shfl_down_sync(0xffffffffu, s[c], off);
            qs[c] += __shfl_down_sync(0xffffffffu, qs[c], off);
        }
    if (te == 0)
#pragma unroll
        for (int c = 0; c < 8; c++) {
            atomicAdd(&g_sum[layer_stats][tc * 8 + c], s[c]);
            atomicAdd(&g_sq[layer_stats][tc * 8 + c], qs[c]);
        }
}

// Layer 1: gather P[dst]+Q[src], BN0+ReLU -> Ht (col-major), f32x2 GEMM with W1 -> g_Y, stats1.
__global__ void __launch_bounds__(256) k_layer1(const float* __restrict__ W1) {
    __shared__ float Ht[CC][128];
    __shared__ float Ws[CC][CC];
    int t = threadIdx.x;
#pragma unroll
    for (int i = 0; i < 16; i++)
        ((float*)Ws)[t + i * 256] = W1[t + i * 256];

    int e0 = blockIdx.x * 128;
    int le = t & 127, half = t >> 7;
    int e = e0 + le;
    int dst = g_dst[e], src = g_src[e];
    const float4* Pp = (const float4*)&g_P[dst * CC + half * 32];
    const float4* Qp = (const float4*)&g_Q[src * CC + half * 32];
#pragma unroll
    for (int i = 0; i < 8; i++) {
        float4 p = Pp[i], qv = Qp[i];
        int c = half * 32 + i * 4;
        float4 A = *(const float4*)&g_bnA[0][c];
        float4 B = *(const float4*)&g_bnB[0][c];
        Ht[c + 0][le] = fmaxf(fmaf(A.x, p.x + qv.x, B.x), 0.0f);
        Ht[c + 1][le] = fmaxf(fmaf(A.y, p.y + qv.y, B.y), 0.0f);
        Ht[c + 2][le] = fmaxf(fmaf(A.z, p.z + qv.z, B.z), 0.0f);
        Ht[c + 3][le] = fmaxf(fmaf(A.w, p.w + qv.w, B.w), 0.0f);
    }
    __syncthreads();
    gemm_core_store_stats(Ht, Ws, e0, t, g_Y, 1);
}

// Layer 2: read y1, BN1+ReLU -> Ht, f32x2 GEMM with W2 -> outE, stats2.
__global__ void __launch_bounds__(256) k_layer2(const float* __restrict__ W2,
                                                float* __restrict__ outE) {
    __shared__ float Ht[CC][128];
    __shared__ float Ws[CC][CC];
    int t = threadIdx.x;
#pragma unroll
    for (int i = 0; i < 16; i++)
        ((float*)Ws)[t + i * 256] = W2[t + i * 256];

    int e0 = blockIdx.x * 128;
    int le = t & 127, half = t >> 7;
    const float4* Yp = (const float4*)&g_Y[(size_t)(e0 + le) * CC + half * 32];
#pragma unroll
    for (int i = 0; i < 8; i++) {
        float4 v = Yp[i];
        int c = half * 32 + i * 4;
        float4 A = *(const float4*)&g_bnA[1][c];
        float4 B = *(const float4*)&g_bnB[1][c];
        Ht[c + 0][le] = fmaxf(fmaf(A.x, v.x, B.x), 0.0f);
        Ht[c + 1][le] = fmaxf(fmaf(A.y, v.y, B.y), 0.0f);
        Ht[c + 2][le] = fmaxf(fmaf(A.z, v.z, B.z), 0.0f);
        Ht[c + 3][le] = fmaxf(fmaf(A.w, v.w, B.w), 0.0f);
    }
    __syncthreads();
    gemm_core_store_stats(Ht, Ws, e0, t, outE, 2);
}

// BN2 + ReLU in place on edge activations, then atomic scatter-add into node sums.
__global__ void k_scatter(float* __restrict__ out) {
    int i = blockIdx.x * 256 + threadIdx.x;
    if (i >= EE * 16) return;
    int e = i >> 4, q = i & 15;
    float* oe = out + NN * CC;
    float4 v = *(float4*)&oe[(size_t)e * CC + q * 4];
    float4 A = *(const float4*)&g_bnA[2][q * 4];
    float4 B = *(const float4*)&g_bnB[2][q * 4];
    v.x = fmaxf(fmaf(A.x, v.x, B.x), 0.0f);
    v.y = fmaxf(fmaf(A.y, v.y, B.y), 0.0f);
    v.z = fmaxf(fmaf(A.z, v.z, B.z), 0.0f);
    v.w = fmaxf(fmaf(A.w, v.w, B.w), 0.0f);
    *(float4*)&oe[(size_t)e * CC + q * 4] = v;
    int dst = g_dst[e];
    float* a = out + dst * CC + q * 4;
    atomicAdd(a + 0, v.x);
    atomicAdd(a + 1, v.y);
    atomicAdd(a + 2, v.z);
    atomicAdd(a + 3, v.w);
}

__global__ void k_div(float* __restrict__ out) {
    int i = blockIdx.x * 256 + threadIdx.x;
    if (i < NN * CC) {
        float c = g_cnt[i >> 6];
        out[i] = out[i] / fmaxf(c, 1.0f);
    }
}

extern "C" void kernel_launch(void* const* d_in, const int* in_sizes, int n_in,
                              void* d_out, int out_size) {
    const float* x = (const float*)d_in[0];
    const void* ei = d_in[1];
    const float* W0 = (const float*)d_in[2];
    const float* g0 = (const float*)d_in[4];
    const float* be0 = (const float*)d_in[5];
    const float* W1 = (const float*)d_in[6];
    const float* g1 = (const float*)d_in[8];
    const float* be1 = (const float*)d_in[9];
    const float* W2 = (const float*)d_in[10];
    const float* g2 = (const float*)d_in[12];
    const float* be2 = (const float*)d_in[13];
    float* out = (float*)d_out;
    float* outE = out + NN * CC;

    k_zero<<<(NN * CC + 255) / 256, 256>>>(out);
    k_detect<<<1, 256>>>((const unsigned*)ei);
    k_convert<<<(EE + 255) / 256, 256>>>(ei);
    k_node<<<(NN + 31) / 32, 256>>>(x, W0);
    k_stats0<<<2048, 256>>>();
    k_finalize<<<1, 64>>>(0, g0, be0);
    k_layer1<<<EE / 128, 256>>>(W1);
    k_finalize<<<1, 64>>>(1, g1, be1);
    k_layer2<<<EE / 128, 256>>>(W2, outE);
    k_finalize<<<1, 64>>>(2, g2, be2);
    k_scatter<<<(EE * 16 + 255) / 256, 256>>>(out);
    k_div<<<(NN * CC + 255) / 256, 256>>>(out);
}

// round 4
// speedup vs baseline: 1.1816x; 1.1816x over previous
#include <cuda_runtime.h>
#include <cstdint>

#define NN 50000
#define EE 800000
#define CC 64
#define BN_EPS 1e-5f

// ---------------- scratch (static __device__ globals; no allocation) ----------------
static __device__ __align__(16) float g_P[NN * CC];      // x @ W0[:64]
static __device__ __align__(16) float g_Q[NN * CC];      // x @ W0[64:]
static __device__ __align__(16) float g_Y[EE * CC];      // y1 scratch (pre-BN layer1 output)
static __device__ float g_cnt[NN];                       // dst degree (float)
static __device__ int   g_src[EE];
static __device__ int   g_dst[EE];
static __device__ __align__(16) float g_sum[3][CC];
static __device__ __align__(16) float g_sq[3][CC];
static __device__ __align__(16) float g_bnA[3][CC];      // g * rsqrt(var+eps)
static __device__ __align__(16) float g_bnB[3][CC];      // beta - mean*A
static __device__ int   g_is64;

// ---------------- kernels ----------------

__global__ void k_zero(float* __restrict__ out_nodes) {
    int i = blockIdx.x * 256 + threadIdx.x;
    if (i < NN * CC) out_nodes[i] = 0.0f;
    if (i < NN) g_cnt[i] = 0.0f;
    if (i < 3 * CC) {
        ((float*)g_sum)[i] = 0.0f;
        ((float*)g_sq)[i] = 0.0f;
    }
}

// Detect whether edge_index is int64 (odd 32-bit words all zero) or int32.
__global__ void k_detect(const unsigned* __restrict__ w) {
    __shared__ int bad;
    if (threadIdx.x == 0) bad = 0;
    __syncthreads();
    int b = 0;
    for (int i = threadIdx.x; i < 1024; i += 256)
        if (w[2 * i + 1] != 0u) b = 1;
    if (b) atomicOr(&bad, 1);
    __syncthreads();
    if (threadIdx.x == 0) g_is64 = bad ? 0 : 1;
}

__global__ void k_convert(const void* __restrict__ ei) {
    int e = blockIdx.x * 256 + threadIdx.x;
    if (e >= EE) return;
    int s, d;
    if (g_is64) {
        const long long* p = (const long long*)ei;
        s = (int)p[e];
        d = (int)p[EE + e];
    } else {
        const int* p = (const int*)ei;
        s = p[e];
        d = p[EE + e];
    }
    g_src[e] = s;
    g_dst[e] = d;
}

// Node-level GEMM: P = x @ W0[:64], Q = x @ W0[64:].  Tile: 32 nodes x 128 cols per block.
__global__ void __launch_bounds__(256) k_node(const float* __restrict__ x,
                                              const float* __restrict__ W0) {
    __shared__ float sW[64][128];   // cols 0..63 = W0a, 64..127 = W0b
    __shared__ float sx[32][64];
    int t = threadIdx.x;
#pragma unroll
    for (int i = 0; i < 32; i++) {
        int idx = t + i * 256;      // 0..8191
        int k = idx >> 7;
        int cc = idx & 127;
        sW[k][cc] = (cc < 64) ? W0[k * 64 + cc] : W0[(64 + k) * 64 + (cc - 64)];
    }
    int n0 = blockIdx.x * 32;
#pragma unroll
    for (int i = 0; i < 8; i++) {
        int idx = t + i * 256;      // 0..2047
        int nl = idx >> 6;
        int k = idx & 63;
        int n = n0 + nl;
        sx[nl][k] = (n < NN) ? x[n * 64 + k] : 0.0f;
    }
    __syncthreads();
    int tc = t & 31;                // 4 cols each -> 128 cols
    int tn = t >> 5;                // 4 nodes each -> 32 nodes
    float acc[4][4] = {};
#pragma unroll 16
    for (int k = 0; k < 64; k++) {
        float4 w = *(const float4*)&sW[k][tc * 4];
        float x0 = sx[tn * 4 + 0][k];
        float x1 = sx[tn * 4 + 1][k];
        float x2 = sx[tn * 4 + 2][k];
        float x3 = sx[tn * 4 + 3][k];
        acc[0][0] = fmaf(x0, w.x, acc[0][0]); acc[0][1] = fmaf(x0, w.y, acc[0][1]);
        acc[0][2] = fmaf(x0, w.z, acc[0][2]); acc[0][3] = fmaf(x0, w.w, acc[0][3]);
        acc[1][0] = fmaf(x1, w.x, acc[1][0]); acc[1][1] = fmaf(x1, w.y, acc[1][1]);
        acc[1][2] = fmaf(x1, w.z, acc[1][2]); acc[1][3] = fmaf(x1, w.w, acc[1][3]);
        acc[2][0] = fmaf(x2, w.x, acc[2][0]); acc[2][1] = fmaf(x2, w.y, acc[2][1]);
        acc[2][2] = fmaf(x2, w.z, acc[2][2]); acc[2][3] = fmaf(x2, w.w, acc[2][3]);
        acc[3][0] = fmaf(x3, w.x, acc[3][0]); acc[3][1] = fmaf(x3, w.y, acc[3][1]);
        acc[3][2] = fmaf(x3, w.z, acc[3][2]); acc[3][3] = fmaf(x3, w.w, acc[3][3]);
    }
#pragma unroll
    for (int i = 0; i < 4; i++) {
        int n = n0 + tn * 4 + i;
        if (n < NN) {
            float4 v = make_float4(acc[i][0], acc[i][1], acc[i][2], acc[i][3]);
            if (tc < 16)
                *(float4*)&g_P[n * 64 + tc * 4] = v;
            else
                *(float4*)&g_Q[n * 64 + (tc - 16) * 4] = v;
        }
    }
}

// Layer-0 stats: per-column sum/sumsq of y0 = P[dst]+Q[src]; also dst degree counts.
__global__ void k_stats0() {
    __shared__ float ss[CC], sq[CC];
    int t = threadIdx.x;
    if (t < CC) { ss[t] = 0.0f; sq[t] = 0.0f; }
    __syncthreads();
    int lane = t & 31;
    int warp = (blockIdx.x * 256 + t) >> 5;
    int nw = (gridDim.x * 256) >> 5;
    float2 s = make_float2(0.0f, 0.0f), q = make_float2(0.0f, 0.0f);
    for (int e = warp; e < EE; e += nw) {
        int dst = g_dst[e], src = g_src[e];
        float2 p = *(const float2*)&g_P[dst * CC + 2 * lane];
        float2 qq = *(const float2*)&g_Q[src * CC + 2 * lane];
        float y0 = p.x + qq.x, y1 = p.y + qq.y;
        s.x += y0; s.y += y1;
        q.x = fmaf(y0, y0, q.x); q.y = fmaf(y1, y1, q.y);
        if (lane == 0) atomicAdd(&g_cnt[dst], 1.0f);
    }
    atomicAdd(&ss[2 * lane], s.x);
    atomicAdd(&ss[2 * lane + 1], s.y);
    atomicAdd(&sq[2 * lane], q.x);
    atomicAdd(&sq[2 * lane + 1], q.y);
    __syncthreads();
    if (t < CC) {
        atomicAdd(&g_sum[0][t], ss[t]);
        atomicAdd(&g_sq[0][t], sq[t]);
    }
}

__global__ void k_finalize(int layer, const float* __restrict__ gam,
                           const float* __restrict__ bet) {
    int c = threadIdx.x;
    float inv = 1.0f / (float)EE;
    float m = g_sum[layer][c] * inv;
    float v = g_sq[layer][c] * inv - m * m;
    float a = gam[c] * rsqrtf(v + BN_EPS);
    g_bnA[layer][c] = a;
    g_bnB[layer][c] = bet[c] - m * a;
}

// Layer 1: per 64-edge tile: gather P[dst]+Q[src], BN0+ReLU -> Ht (transposed smem),
// GEMM with W1 -> y1 to g_Y, accumulate stats1.
__global__ void __launch_bounds__(256) k_layer1(const float* __restrict__ W1) {
    __shared__ float Ht[CC][68];
    __shared__ float Ws[CC][CC];
    __shared__ float ssum[CC], ssq[CC];
    int t = threadIdx.x;
#pragma unroll
    for (int i = 0; i < 16; i++)
        ((float*)Ws)[t + i * 256] = W1[t + i * 256];
    if (t < CC) { ssum[t] = 0.0f; ssq[t] = 0.0f; }

    int e0 = blockIdx.x * 64;
    int le = t & 63, half = t >> 6;
    int e = e0 + le;
    int dst = g_dst[e], src = g_src[e];
    const float4* Pp = (const float4*)&g_P[dst * CC + half * 16];
    const float4* Qp = (const float4*)&g_Q[src * CC + half * 16];
#pragma unroll
    for (int i = 0; i < 4; i++) {
        float4 p = Pp[i], qv = Qp[i];
        int c = half * 16 + i * 4;
        float4 A = *(const float4*)&g_bnA[0][c];
        float4 B = *(const float4*)&g_bnB[0][c];
        Ht[c + 0][le] = fmaxf(fmaf(A.x, p.x + qv.x, B.x), 0.0f);
        Ht[c + 1][le] = fmaxf(fmaf(A.y, p.y + qv.y, B.y), 0.0f);
        Ht[c + 2][le] = fmaxf(fmaf(A.z, p.z + qv.z, B.z), 0.0f);
        Ht[c + 3][le] = fmaxf(fmaf(A.w, p.w + qv.w, B.w), 0.0f);
    }
    __syncthreads();

    int te = t & 15, tc = t >> 4;
    float acc[4][4] = {};
#pragma unroll 16
    for (int k = 0; k < CC; k++) {
        float4 h = *(const float4*)&Ht[k][te * 4];
        float4 w = *(const float4*)&Ws[k][tc * 4];
        acc[0][0] = fmaf(h.x, w.x, acc[0][0]); acc[0][1] = fmaf(h.x, w.y, acc[0][1]);
        acc[0][2] = fmaf(h.x, w.z, acc[0][2]); acc[0][3] = fmaf(h.x, w.w, acc[0][3]);
        acc[1][0] = fmaf(h.y, w.x, acc[1][0]); acc[1][1] = fmaf(h.y, w.y, acc[1][1]);
        acc[1][2] = fmaf(h.y, w.z, acc[1][2]); acc[1][3] = fmaf(h.y, w.w, acc[1][3]);
        acc[2][0] = fmaf(h.z, w.x, acc[2][0]); acc[2][1] = fmaf(h.z, w.y, acc[2][1]);
        acc[2][2] = fmaf(h.z, w.z, acc[2][2]); acc[2][3] = fmaf(h.z, w.w, acc[2][3]);
        acc[3][0] = fmaf(h.w, w.x, acc[3][0]); acc[3][1] = fmaf(h.w, w.y, acc[3][1]);
        acc[3][2] = fmaf(h.w, w.z, acc[3][2]); acc[3][3] = fmaf(h.w, w.w, acc[3][3]);
    }
#pragma unroll
    for (int i = 0; i < 4; i++) {
        int ee2 = e0 + te * 4 + i;
        *(float4*)&g_Y[(size_t)ee2 * CC + tc * 4] =
            make_float4(acc[i][0], acc[i][1], acc[i][2], acc[i][3]);
    }
    float ps[4], pq[4];
#pragma unroll
    for (int j = 0; j < 4; j++) {
        ps[j] = acc[0][j] + acc[1][j] + acc[2][j] + acc[3][j];
        pq[j] = acc[0][j] * acc[0][j] + acc[1][j] * acc[1][j] +
                acc[2][j] * acc[2][j] + acc[3][j] * acc[3][j];
    }
#pragma unroll
    for (int off = 8; off > 0; off >>= 1) {
#pragma unroll
        for (int j = 0; j < 4; j++) {
            ps[j] += __shfl_down_sync(0xffffffffu, ps[j], off, 16);
            pq[j] += __shfl_down_sync(0xffffffffu, pq[j], off, 16);
        }
    }
    if (te == 0) {
#pragma unroll
        for (int j = 0; j < 4; j++) {
            atomicAdd(&ssum[tc * 4 + j], ps[j]);
            atomicAdd(&ssq[tc * 4 + j], pq[j]);
        }
    }
    __syncthreads();
    if (t < CC) {
        atomicAdd(&g_sum[1][t], ssum[t]);
        atomicAdd(&g_sq[1][t], ssq[t]);
    }
}

// Layer 2: read y1, BN1+ReLU -> Ht, GEMM with W2 -> y2 into d_out edge region, stats2.
__global__ void __launch_bounds__(256) k_layer2(const float* __restrict__ W2,
                                                float* __restrict__ outE) {
    __shared__ float Ht[CC][68];
    __shared__ float Ws[CC][CC];
    __shared__ float ssum[CC], ssq[CC];
    int t = threadIdx.x;
#pragma unroll
    for (int i = 0; i < 16; i++)
        ((float*)Ws)[t + i * 256] = W2[t + i * 256];
    if (t < CC) { ssum[t] = 0.0f; ssq[t] = 0.0f; }

    int e0 = blockIdx.x * 64;
    int cfix = t & 63;
    float A = g_bnA[1][cfix], Bb = g_bnB[1][cfix];
#pragma unroll
    for (int j = 0; j < 16; j++) {
        int idx = t + j * 256;
        int lel = (t >> 6) + j * 4;
        float v = g_Y[(size_t)e0 * CC + idx];
        Ht[cfix][lel] = fmaxf(fmaf(A, v, Bb), 0.0f);
    }
    __syncthreads();

    int te = t & 15, tc = t >> 4;
    float acc[4][4] = {};
#pragma unroll 16
    for (int k = 0; k < CC; k++) {
        float4 h = *(const float4*)&Ht[k][te * 4];
        float4 w = *(const float4*)&Ws[k][tc * 4];
        acc[0][0] = fmaf(h.x, w.x, acc[0][0]); acc[0][1] = fmaf(h.x, w.y, acc[0][1]);
        acc[0][2] = fmaf(h.x, w.z, acc[0][2]); acc[0][3] = fmaf(h.x, w.w, acc[0][3]);
        acc[1][0] = fmaf(h.y, w.x, acc[1][0]); acc[1][1] = fmaf(h.y, w.y, acc[1][1]);
        acc[1][2] = fmaf(h.y, w.z, acc[1][2]); acc[1][3] = fmaf(h.y, w.w, acc[1][3]);
        acc[2][0] = fmaf(h.z, w.x, acc[2][0]); acc[2][1] = fmaf(h.z, w.y, acc[2][1]);
        acc[2][2] = fmaf(h.z, w.z, acc[2][2]); acc[2][3] = fmaf(h.z, w.w, acc[2][3]);
        acc[3][0] = fmaf(h.w, w.x, acc[3][0]); acc[3][1] = fmaf(h.w, w.y, acc[3][1]);
        acc[3][2] = fmaf(h.w, w.z, acc[3][2]); acc[3][3] = fmaf(h.w, w.w, acc[3][3]);
    }
#pragma unroll
    for (int i = 0; i < 4; i++) {
        int ee2 = e0 + te * 4 + i;
        *(float4*)&outE[(size_t)ee2 * CC + tc * 4] =
            make_float4(acc[i][0], acc[i][1], acc[i][2], acc[i][3]);
    }
    float ps[4], pq[4];
#pragma unroll
    for (int j = 0; j < 4; j++) {
        ps[j] = acc[0][j] + acc[1][j] + acc[2][j] + acc[3][j];
        pq[j] = acc[0][j] * acc[0][j] + acc[1][j] * acc[1][j] +
                acc[2][j] * acc[2][j] + acc[3][j] * acc[3][j];
    }
#pragma unroll
    for (int off = 8; off > 0; off >>= 1) {
#pragma unroll
        for (int j = 0; j < 4; j++) {
            ps[j] += __shfl_down_sync(0xffffffffu, ps[j], off, 16);
            pq[j] += __shfl_down_sync(0xffffffffu, pq[j], off, 16);
        }
    }
    if (te == 0) {
#pragma unroll
        for (int j = 0; j < 4; j++) {
            atomicAdd(&ssum[tc * 4 + j], ps[j]);
            atomicAdd(&ssq[tc * 4 + j], pq[j]);
        }
    }
    __syncthreads();
    if (t < CC) {
        atomicAdd(&g_sum[2][t], ssum[t]);
        atomicAdd(&g_sq[2][t], ssq[t]);
    }
}

// BN2 + ReLU in place on edge activations, then vector red.v4 scatter into node sums.
// Thread = (edge, 16-float quarter): 4x LDG.128 + 4x STG.128 + 4x RED.v4 + 1x LDG.
__global__ void k_scatter(float* __restrict__ out) {
    int i = blockIdx.x * 256 + threadIdx.x;
    if (i >= EE * 4) return;
    int e = i >> 2, q = i & 3;              // quarter = 16 floats
    float* oe = out + (size_t)NN * CC + (size_t)e * CC + q * 16;
    int dst = g_dst[e];
    float* a = out + (size_t)dst * CC + q * 16;
#pragma unroll
    for (int j = 0; j < 4; j++) {
        float4 v = *(float4*)&oe[j * 4];
        float4 A = *(const float4*)&g_bnA[2][q * 16 + j * 4];
        float4 B = *(const float4*)&g_bnB[2][q * 16 + j * 4];
        v.x = fmaxf(fmaf(A.x, v.x, B.x), 0.0f);
        v.y = fmaxf(fmaf(A.y, v.y, B.y), 0.0f);
        v.z = fmaxf(fmaf(A.z, v.z, B.z), 0.0f);
        v.w = fmaxf(fmaf(A.w, v.w, B.w), 0.0f);
        *(float4*)&oe[j * 4] = v;
        asm volatile("red.global.add.v4.f32 [%0], {%1, %2, %3, %4};"
                     :: "l"(a + j * 4), "f"(v.x), "f"(v.y), "f"(v.z), "f"(v.w)
                     : "memory");
    }
}

__global__ void k_div(float* __restrict__ out) {
    int i = blockIdx.x * 256 + threadIdx.x;
    if (i < NN * CC) {
        float c = g_cnt[i >> 6];
        out[i] = out[i] / fmaxf(c, 1.0f);
    }
}

extern "C" void kernel_launch(void* const* d_in, const int* in_sizes, int n_in,
                              void* d_out, int out_size) {
    const float* x = (const float*)d_in[0];
    const void* ei = d_in[1];
    const float* W0 = (const float*)d_in[2];
    const float* g0 = (const float*)d_in[4];
    const float* be0 = (const float*)d_in[5];
    const float* W1 = (const float*)d_in[6];
    const float* g1 = (const float*)d_in[8];
    const float* be1 = (const float*)d_in[9];
    const float* W2 = (const float*)d_in[10];
    const float* g2 = (const float*)d_in[12];
    const float* be2 = (const float*)d_in[13];
    float* out = (float*)d_out;
    float* outE = out + NN * CC;

    k_zero<<<(NN * CC + 255) / 256, 256>>>(out);
    k_detect<<<1, 256>>>((const unsigned*)ei);
    k_convert<<<(EE + 255) / 256, 256>>>(ei);
    k_node<<<(NN + 31) / 32, 256>>>(x, W0);
    k_stats0<<<2048, 256>>>();
    k_finalize<<<1, 64>>>(0, g0, be0);
    k_layer1<<<EE / 64, 256>>>(W1);
    k_finalize<<<1, 64>>>(1, g1, be1);
    k_layer2<<<EE / 64, 256>>>(W2, outE);
    k_finalize<<<1, 64>>>(2, g2, be2);
    k_scatter<<<(EE * 4 + 255) / 256, 256>>>(out);
    k_div<<<(NN * CC + 255) / 256, 256>>>(out);
}

// round 5
// speedup vs baseline: 1.1835x; 1.0016x over previous
#include <cuda_runtime.h>
#include <cstdint>

#define NN 50000
#define EE 800000
#define CC 64
#define BN_EPS 1e-5f

// ---------------- scratch (static __device__ globals; no allocation) ----------------
static __device__ __align__(16) float g_P[NN * CC];      // x @ W0[:64]
static __device__ __align__(16) float g_Q[NN * CC];      // x @ W0[64:]
static __device__ __align__(16) float g_Y[EE * CC];      // y1 scratch (pre-BN layer1 output)
static __device__ float g_cnt[NN];                       // dst degree (float)
static __device__ int   g_src[EE];
static __device__ int   g_dst[EE];
static __device__ __align__(16) float g_sum[3][CC];
static __device__ __align__(16) float g_sq[3][CC];
static __device__ __align__(16) float g_bnA[3][CC];      // g * rsqrt(var+eps)
static __device__ __align__(16) float g_bnB[3][CC];      // beta - mean*A
static __device__ int   g_is64;

// ---------------- kernels ----------------

__global__ void k_zero(float* __restrict__ out_nodes) {
    int i = blockIdx.x * 256 + threadIdx.x;
    if (i < NN * CC) out_nodes[i] = 0.0f;
    if (i < NN) g_cnt[i] = 0.0f;
    if (i < 3 * CC) {
        ((float*)g_sum)[i] = 0.0f;
        ((float*)g_sq)[i] = 0.0f;
    }
}

// Detect whether edge_index is int64 (odd 32-bit words all zero) or int32.
__global__ void k_detect(const unsigned* __restrict__ w) {
    __shared__ int bad;
    if (threadIdx.x == 0) bad = 0;
    __syncthreads();
    int b = 0;
    for (int i = threadIdx.x; i < 1024; i += 256)
        if (w[2 * i + 1] != 0u) b = 1;
    if (b) atomicOr(&bad, 1);
    __syncthreads();
    if (threadIdx.x == 0) g_is64 = bad ? 0 : 1;
}

__global__ void k_convert(const void* __restrict__ ei) {
    int e = blockIdx.x * 256 + threadIdx.x;
    if (e >= EE) return;
    int s, d;
    if (g_is64) {
        const long long* p = (const long long*)ei;
        s = (int)p[e];
        d = (int)p[EE + e];
    } else {
        const int* p = (const int*)ei;
        s = p[e];
        d = p[EE + e];
    }
    g_src[e] = s;
    g_dst[e] = d;
}

// Node-level GEMM: P = x @ W0[:64], Q = x @ W0[64:].  Tile: 32 nodes x 128 cols per block.
__global__ void __launch_bounds__(256) k_node(const float* __restrict__ x,
                                              const float* __restrict__ W0) {
    __shared__ float sW[64][128];   // cols 0..63 = W0a, 64..127 = W0b
    __shared__ float sx[32][64];
    int t = threadIdx.x;
#pragma unroll
    for (int i = 0; i < 32; i++) {
        int idx = t + i * 256;      // 0..8191
        int k = idx >> 7;
        int cc = idx & 127;
        sW[k][cc] = (cc < 64) ? W0[k * 64 + cc] : W0[(64 + k) * 64 + (cc - 64)];
    }
    int n0 = blockIdx.x * 32;
#pragma unroll
    for (int i = 0; i < 8; i++) {
        int idx = t + i * 256;      // 0..2047
        int nl = idx >> 6;
        int k = idx & 63;
        int n = n0 + nl;
        sx[nl][k] = (n < NN) ? x[n * 64 + k] : 0.0f;
    }
    __syncthreads();
    int tc = t & 31;                // 4 cols each -> 128 cols
    int tn = t >> 5;                // 4 nodes each -> 32 nodes
    float acc[4][4] = {};
#pragma unroll 16
    for (int k = 0; k < 64; k++) {
        float4 w = *(const float4*)&sW[k][tc * 4];
        float x0 = sx[tn * 4 + 0][k];
        float x1 = sx[tn * 4 + 1][k];
        float x2 = sx[tn * 4 + 2][k];
        float x3 = sx[tn * 4 + 3][k];
        acc[0][0] = fmaf(x0, w.x, acc[0][0]); acc[0][1] = fmaf(x0, w.y, acc[0][1]);
        acc[0][2] = fmaf(x0, w.z, acc[0][2]); acc[0][3] = fmaf(x0, w.w, acc[0][3]);
        acc[1][0] = fmaf(x1, w.x, acc[1][0]); acc[1][1] = fmaf(x1, w.y, acc[1][1]);
        acc[1][2] = fmaf(x1, w.z, acc[1][2]); acc[1][3] = fmaf(x1, w.w, acc[1][3]);
        acc[2][0] = fmaf(x2, w.x, acc[2][0]); acc[2][1] = fmaf(x2, w.y, acc[2][1]);
        acc[2][2] = fmaf(x2, w.z, acc[2][2]); acc[2][3] = fmaf(x2, w.w, acc[2][3]);
        acc[3][0] = fmaf(x3, w.x, acc[3][0]); acc[3][1] = fmaf(x3, w.y, acc[3][1]);
        acc[3][2] = fmaf(x3, w.z, acc[3][2]); acc[3][3] = fmaf(x3, w.w, acc[3][3]);
    }
#pragma unroll
    for (int i = 0; i < 4; i++) {
        int n = n0 + tn * 4 + i;
        if (n < NN) {
            float4 v = make_float4(acc[i][0], acc[i][1], acc[i][2], acc[i][3]);
            if (tc < 16)
                *(float4*)&g_P[n * 64 + tc * 4] = v;
            else
                *(float4*)&g_Q[n * 64 + (tc - 16) * 4] = v;
        }
    }
}

// Layer-0 stats: per-column sum/sumsq of y0 = P[dst]+Q[src]; also dst degree counts.
__global__ void k_stats0() {
    __shared__ float ss[CC], sq[CC];
    int t = threadIdx.x;
    if (t < CC) { ss[t] = 0.0f; sq[t] = 0.0f; }
    __syncthreads();
    int lane = t & 31;
    int warp = (blockIdx.x * 256 + t) >> 5;
    int nw = (gridDim.x * 256) >> 5;
    float2 s = make_float2(0.0f, 0.0f), q = make_float2(0.0f, 0.0f);
    for (int e = warp; e < EE; e += nw) {
        int dst = g_dst[e], src = g_src[e];
        float2 p = *(const float2*)&g_P[dst * CC + 2 * lane];
        float2 qq = *(const float2*)&g_Q[src * CC + 2 * lane];
        float y0 = p.x + qq.x, y1 = p.y + qq.y;
        s.x += y0; s.y += y1;
        q.x = fmaf(y0, y0, q.x); q.y = fmaf(y1, y1, q.y);
        if (lane == 0) atomicAdd(&g_cnt[dst], 1.0f);
    }
    atomicAdd(&ss[2 * lane], s.x);
    atomicAdd(&ss[2 * lane + 1], s.y);
    atomicAdd(&sq[2 * lane], q.x);
    atomicAdd(&sq[2 * lane + 1], q.y);
    __syncthreads();
    if (t < CC) {
        atomicAdd(&g_sum[0][t], ss[t]);
        atomicAdd(&g_sq[0][t], sq[t]);
    }
}

__global__ void k_finalize(int layer, const float* __restrict__ gam,
                           const float* __restrict__ bet) {
    int c = threadIdx.x;
    float inv = 1.0f / (float)EE;
    float m = g_sum[layer][c] * inv;
    float v = g_sq[layer][c] * inv - m * m;
    float a = gam[c] * rsqrtf(v + BN_EPS);
    g_bnA[layer][c] = a;
    g_bnB[layer][c] = bet[c] - m * a;
}

// Layer 1: per 64-edge tile: gather P[dst]+Q[src], BN0+ReLU -> Ht (transposed smem),
// GEMM with W1 -> y1 to g_Y, accumulate stats1.
__global__ void __launch_bounds__(256) k_layer1(const float* __restrict__ W1) {
    __shared__ float Ht[CC][68];
    __shared__ float Ws[CC][CC];
    __shared__ float ssum[CC], ssq[CC];
    int t = threadIdx.x;
#pragma unroll
    for (int i = 0; i < 16; i++)
        ((float*)Ws)[t + i * 256] = W1[t + i * 256];
    if (t < CC) { ssum[t] = 0.0f; ssq[t] = 0.0f; }

    int e0 = blockIdx.x * 64;
    int le = t & 63, half = t >> 6;
    int e = e0 + le;
    int dst = g_dst[e], src = g_src[e];
    const float4* Pp = (const float4*)&g_P[dst * CC + half * 16];
    const float4* Qp = (const float4*)&g_Q[src * CC + half * 16];
#pragma unroll
    for (int i = 0; i < 4; i++) {
        float4 p = Pp[i], qv = Qp[i];
        int c = half * 16 + i * 4;
        float4 A = *(const float4*)&g_bnA[0][c];
        float4 B = *(const float4*)&g_bnB[0][c];
        Ht[c + 0][le] = fmaxf(fmaf(A.x, p.x + qv.x, B.x), 0.0f);
        Ht[c + 1][le] = fmaxf(fmaf(A.y, p.y + qv.y, B.y), 0.0f);
        Ht[c + 2][le] = fmaxf(fmaf(A.z, p.z + qv.z, B.z), 0.0f);
        Ht[c + 3][le] = fmaxf(fmaf(A.w, p.w + qv.w, B.w), 0.0f);
    }
    __syncthreads();

    int te = t & 15, tc = t >> 4;
    float acc[4][4] = {};
#pragma unroll 16
    for (int k = 0; k < CC; k++) {
        float4 h = *(const float4*)&Ht[k][te * 4];
        float4 w = *(const float4*)&Ws[k][tc * 4];
        acc[0][0] = fmaf(h.x, w.x, acc[0][0]); acc[0][1] = fmaf(h.x, w.y, acc[0][1]);
        acc[0][2] = fmaf(h.x, w.z, acc[0][2]); acc[0][3] = fmaf(h.x, w.w, acc[0][3]);
        acc[1][0] = fmaf(h.y, w.x, acc[1][0]); acc[1][1] = fmaf(h.y, w.y, acc[1][1]);
        acc[1][2] = fmaf(h.y, w.z, acc[1][2]); acc[1][3] = fmaf(h.y, w.w, acc[1][3]);
        acc[2][0] = fmaf(h.z, w.x, acc[2][0]); acc[2][1] = fmaf(h.z, w.y, acc[2][1]);
        acc[2][2] = fmaf(h.z, w.z, acc[2][2]); acc[2][3] = fmaf(h.z, w.w, acc[2][3]);
        acc[3][0] = fmaf(h.w, w.x, acc[3][0]); acc[3][1] = fmaf(h.w, w.y, acc[3][1]);
        acc[3][2] = fmaf(h.w, w.z, acc[3][2]); acc[3][3] = fmaf(h.w, w.w, acc[3][3]);
    }
#pragma unroll
    for (int i = 0; i < 4; i++) {
        int ee2 = e0 + te * 4 + i;
        *(float4*)&g_Y[(size_t)ee2 * CC + tc * 4] =
            make_float4(acc[i][0], acc[i][1], acc[i][2], acc[i][3]);
    }
    float ps[4], pq[4];
#pragma unroll
    for (int j = 0; j < 4; j++) {
        ps[j] = acc[0][j] + acc[1][j] + acc[2][j] + acc[3][j];
        pq[j] = acc[0][j] * acc[0][j] + acc[1][j] * acc[1][j] +
                acc[2][j] * acc[2][j] + acc[3][j] * acc[3][j];
    }
#pragma unroll
    for (int off = 8; off > 0; off >>= 1) {
#pragma unroll
        for (int j = 0; j < 4; j++) {
            ps[j] += __shfl_down_sync(0xffffffffu, ps[j], off, 16);
            pq[j] += __shfl_down_sync(0xffffffffu, pq[j], off, 16);
        }
    }
    if (te == 0) {
#pragma unroll
        for (int j = 0; j < 4; j++) {
            atomicAdd(&ssum[tc * 4 + j], ps[j]);
            atomicAdd(&ssq[tc * 4 + j], pq[j]);
        }
    }
    __syncthreads();
    if (t < CC) {
        atomicAdd(&g_sum[1][t], ssum[t]);
        atomicAdd(&g_sq[1][t], ssq[t]);
    }
}

// Layer 2: read y1, BN1+ReLU -> Ht, GEMM with W2 -> y2 into d_out edge region, stats2.
__global__ void __launch_bounds__(256) k_layer2(const float* __restrict__ W2,
                                                float* __restrict__ outE) {
    __shared__ float Ht[CC][68];
    __shared__ float Ws[CC][CC];
    __shared__ float ssum[CC], ssq[CC];
    int t = threadIdx.x;
#pragma unroll
    for (int i = 0; i < 16; i++)
        ((float*)Ws)[t + i * 256] = W2[t + i * 256];
    if (t < CC) { ssum[t] = 0.0f; ssq[t] = 0.0f; }

    int e0 = blockIdx.x * 64;
    int cfix = t & 63;
    float A = g_bnA[1][cfix], Bb = g_bnB[1][cfix];
#pragma unroll
    for (int j = 0; j < 16; j++) {
        int idx = t + j * 256;
        int lel = (t >> 6) + j * 4;
        float v = g_Y[(size_t)e0 * CC + idx];
        Ht[cfix][lel] = fmaxf(fmaf(A, v, Bb), 0.0f);
    }
    __syncthreads();

    int te = t & 15, tc = t >> 4;
    float acc[4][4] = {};
#pragma unroll 16
    for (int k = 0; k < CC; k++) {
        float4 h = *(const float4*)&Ht[k][te * 4];
        float4 w = *(const float4*)&Ws[k][tc * 4];
        acc[0][0] = fmaf(h.x, w.x, acc[0][0]); acc[0][1] = fmaf(h.x, w.y, acc[0][1]);
        acc[0][2] = fmaf(h.x, w.z, acc[0][2]); acc[0][3] = fmaf(h.x, w.w, acc[0][3]);
        acc[1][0] = fmaf(h.y, w.x, acc[1][0]); acc[1][1] = fmaf(h.y, w.y, acc[1][1]);
        acc[1][2] = fmaf(h.y, w.z, acc[1][2]); acc[1][3] = fmaf(h.y, w.w, acc[1][3]);
        acc[2][0] = fmaf(h.z, w.x, acc[2][0]); acc[2][1] = fmaf(h.z, w.y, acc[2][1]);
        acc[2][2] = fmaf(h.z, w.z, acc[2][2]); acc[2][3] = fmaf(h.z, w.w, acc[2][3]);
        acc[3][0] = fmaf(h.w, w.x, acc[3][0]); acc[3][1] = fmaf(h.w, w.y, acc[3][1]);
        acc[3][2] = fmaf(h.w, w.z, acc[3][2]); acc[3][3] = fmaf(h.w, w.w, acc[3][3]);
    }
#pragma unroll
    for (int i = 0; i < 4; i++) {
        int ee2 = e0 + te * 4 + i;
        *(float4*)&outE[(size_t)ee2 * CC + tc * 4] =
            make_float4(acc[i][0], acc[i][1], acc[i][2], acc[i][3]);
    }
    float ps[4], pq[4];
#pragma unroll
    for (int j = 0; j < 4; j++) {
        ps[j] = acc[0][j] + acc[1][j] + acc[2][j] + acc[3][j];
        pq[j] = acc[0][j] * acc[0][j] + acc[1][j] * acc[1][j] +
                acc[2][j] * acc[2][j] + acc[3][j] * acc[3][j];
    }
#pragma unroll
    for (int off = 8; off > 0; off >>= 1) {
#pragma unroll
        for (int j = 0; j < 4; j++) {
            ps[j] += __shfl_down_sync(0xffffffffu, ps[j], off, 16);
            pq[j] += __shfl_down_sync(0xffffffffu, pq[j], off, 16);
        }
    }
    if (te == 0) {
#pragma unroll
        for (int j = 0; j < 4; j++) {
            atomicAdd(&ssum[tc * 4 + j], ps[j]);
            atomicAdd(&ssq[tc * 4 + j], pq[j]);
        }
    }
    __syncthreads();
    if (t < CC) {
        atomicAdd(&g_sum[2][t], ssum[t]);
        atomicAdd(&g_sq[2][t], ssq[t]);
    }
}

// BN2 + ReLU in place on edge activations, then vector red.v4 scatter into node sums.
// Thread = (edge, 16-float quarter): 4x LDG.128 + 4x STG.128 + 4x RED.v4 + 1x LDG.
__global__ void k_scatter(float* __restrict__ out) {
    int i = blockIdx.x * 256 + threadIdx.x;
    if (i >= EE * 4) return;
    int e = i >> 2, q = i & 3;              // quarter = 16 floats
    float* oe = out + (size_t)NN * CC + (size_t)e * CC + q * 16;
    int dst = g_dst[e];
    float* a = out + (size_t)dst * CC + q * 16;
#pragma unroll
    for (int j = 0; j < 4; j++) {
        float4 v = *(float4*)&oe[j * 4];
        float4 A = *(const float4*)&g_bnA[2][q * 16 + j * 4];
        float4 B = *(const float4*)&g_bnB[2][q * 16 + j * 4];
        v.x = fmaxf(fmaf(A.x, v.x, B.x), 0.0f);
        v.y = fmaxf(fmaf(A.y, v.y, B.y), 0.0f);
        v.z = fmaxf(fmaf(A.z, v.z, B.z), 0.0f);
        v.w = fmaxf(fmaf(A.w, v.w, B.w), 0.0f);
        *(float4*)&oe[j * 4] = v;
        asm volatile("red.global.add.v4.f32 [%0], {%1, %2, %3, %4};"
                     :: "l"(a + j * 4), "f"(v.x), "f"(v.y), "f"(v.z), "f"(v.w)
                     : "memory");
    }
}

__global__ void k_div(float* __restrict__ out) {
    int i = blockIdx.x * 256 + threadIdx.x;
    if (i < NN * CC) {
        float c = g_cnt[i >> 6];
        out[i] = out[i] / fmaxf(c, 1.0f);
    }
}

extern "C" void kernel_launch(void* const* d_in, const int* in_sizes, int n_in,
                              void* d_out, int out_size) {
    const float* x = (const float*)d_in[0];
    const void* ei = d_in[1];
    const float* W0 = (const float*)d_in[2];
    const float* g0 = (const float*)d_in[4];
    const float* be0 = (const float*)d_in[5];
    const float* W1 = (const float*)d_in[6];
    const float* g1 = (const float*)d_in[8];
    const float* be1 = (const float*)d_in[9];
    const float* W2 = (const float*)d_in[10];
    const float* g2 = (const float*)d_in[12];
    const float* be2 = (const float*)d_in[13];
    float* out = (float*)d_out;
    float* outE = out + NN * CC;

    k_zero<<<(NN * CC + 255) / 256, 256>>>(out);
    k_detect<<<1, 256>>>((const unsigned*)ei);
    k_convert<<<(EE + 255) / 256, 256>>>(ei);
    k_node<<<(NN + 31) / 32, 256>>>(x, W0);
    k_stats0<<<2048, 256>>>();
    k_finalize<<<1, 64>>>(0, g0, be0);
    k_layer1<<<EE / 64, 256>>>(W1);
    k_finalize<<<1, 64>>>(1, g1, be1);
    k_layer2<<<EE / 64, 256>>>(W2, outE);
    k_finalize<<<1, 64>>>(2, g2, be2);
    k_scatter<<<(EE * 4 + 255) / 256, 256>>>(out);
    k_div<<<(NN * CC + 255) / 256, 256>>>(out);
}

// round 7
// speedup vs baseline: 1.3867x; 1.1717x over previous
#include <cuda_runtime.h>
#include <cuda_bf16.h>
#include <mma.h>
#include <cstdint>

using namespace nvcuda;

#define NN 50000
#define EE 800000
#define CC 64
#define BN_EPS 1e-5f

// ---------------- scratch (static __device__ globals; no allocation) ----------------
static __device__ __align__(16) float g_P[NN * CC];      // x @ W0[:64]
static __device__ __align__(16) float g_Q[NN * CC];      // x @ W0[64:]
static __device__ __align__(16) float g_Y[EE * CC];      // y1 scratch (pre-BN layer1 output)
static __device__ float g_cnt[NN];
static __device__ int   g_src[EE];
static __device__ int   g_dst[EE];
static __device__ __align__(16) float g_sum[3][CC];
static __device__ __align__(16) float g_sq[3][CC];
static __device__ __align__(16) float g_bnA[3][CC];
static __device__ __align__(16) float g_bnB[3][CC];
static __device__ int   g_is64;
// bf16 hi/lo split of W1/W2 (row-major [k][n])
static __device__ __align__(16) __nv_bfloat16 g_Whi[2][4096];
static __device__ __align__(16) __nv_bfloat16 g_Wlo[2][4096];

// ---------------- smem layout for wmma layer kernel (bytes) ----------------
#define LDA 72          // bf16 elements per A row (padded)
#define LDB 72          // bf16 elements per B row (padded)
#define LDS_F 68        // fp32 elements per stage row (padded)
#define O_AHI 0
#define O_ALO 18432     // 128*72*2
#define O_BHI 36864
#define O_BLO 46080     // +64*72*2
#define SMEM_LK 55296

// ---------------- basic kernels (round-5 known-good) ----------------

__global__ void k_zero(float* __restrict__ out_nodes) {
    int i = blockIdx.x * 256 + threadIdx.x;
    if (i < NN * CC) out_nodes[i] = 0.0f;
    if (i < NN) g_cnt[i] = 0.0f;
    if (i < 3 * CC) {
        ((float*)g_sum)[i] = 0.0f;
        ((float*)g_sq)[i] = 0.0f;
    }
}

__global__ void k_detect(const unsigned* __restrict__ w) {
    __shared__ int bad;
    if (threadIdx.x == 0) bad = 0;
    __syncthreads();
    int b = 0;
    for (int i = threadIdx.x; i < 1024; i += 256)
        if (w[2 * i + 1] != 0u) b = 1;
    if (b) atomicOr(&bad, 1);
    __syncthreads();
    if (threadIdx.x == 0) g_is64 = bad ? 0 : 1;
}

__global__ void k_convert(const void* __restrict__ ei) {
    int e = blockIdx.x * 256 + threadIdx.x;
    if (e >= EE) return;
    int s, d;
    if (g_is64) {
        const long long* p = (const long long*)ei;
        s = (int)p[e];
        d = (int)p[EE + e];
    } else {
        const int* p = (const int*)ei;
        s = p[e];
        d = p[EE + e];
    }
    g_src[e] = s;
    g_dst[e] = d;
}

// Node-level GEMM: P = x @ W0[:64], Q = x @ W0[64:].
__global__ void __launch_bounds__(256) k_node(const float* __restrict__ x,
                                              const float* __restrict__ W0) {
    __shared__ float sW[64][128];
    __shared__ float sx[32][64];
    int t = threadIdx.x;
#pragma unroll
    for (int i = 0; i < 32; i++) {
        int idx = t + i * 256;
        int k = idx >> 7;
        int cc = idx & 127;
        sW[k][cc] = (cc < 64) ? W0[k * 64 + cc] : W0[(64 + k) * 64 + (cc - 64)];
    }
    int n0 = blockIdx.x * 32;
#pragma unroll
    for (int i = 0; i < 8; i++) {
        int idx = t + i * 256;
        int nl = idx >> 6;
        int k = idx & 63;
        int n = n0 + nl;
        sx[nl][k] = (n < NN) ? x[n * 64 + k] : 0.0f;
    }
    __syncthreads();
    int tc = t & 31;
    int tn = t >> 5;
    float acc[4][4] = {};
#pragma unroll 16
    for (int k = 0; k < 64; k++) {
        float4 w = *(const float4*)&sW[k][tc * 4];
        float x0 = sx[tn * 4 + 0][k];
        float x1 = sx[tn * 4 + 1][k];
        float x2 = sx[tn * 4 + 2][k];
        float x3 = sx[tn * 4 + 3][k];
        acc[0][0] = fmaf(x0, w.x, acc[0][0]); acc[0][1] = fmaf(x0, w.y, acc[0][1]);
        acc[0][2] = fmaf(x0, w.z, acc[0][2]); acc[0][3] = fmaf(x0, w.w, acc[0][3]);
        acc[1][0] = fmaf(x1, w.x, acc[1][0]); acc[1][1] = fmaf(x1, w.y, acc[1][1]);
        acc[1][2] = fmaf(x1, w.z, acc[1][2]); acc[1][3] = fmaf(x1, w.w, acc[1][3]);
        acc[2][0] = fmaf(x2, w.x, acc[2][0]); acc[2][1] = fmaf(x2, w.y, acc[2][1]);
        acc[2][2] = fmaf(x2, w.z, acc[2][2]); acc[2][3] = fmaf(x2, w.w, acc[2][3]);
        acc[3][0] = fmaf(x3, w.x, acc[3][0]); acc[3][1] = fmaf(x3, w.y, acc[3][1]);
        acc[3][2] = fmaf(x3, w.z, acc[3][2]); acc[3][3] = fmaf(x3, w.w, acc[3][3]);
    }
#pragma unroll
    for (int i = 0; i < 4; i++) {
        int n = n0 + tn * 4 + i;
        if (n < NN) {
            float4 v = make_float4(acc[i][0], acc[i][1], acc[i][2], acc[i][3]);
            if (tc < 16)
                *(float4*)&g_P[n * 64 + tc * 4] = v;
            else
                *(float4*)&g_Q[n * 64 + (tc - 16) * 4] = v;
        }
    }
}

__global__ void k_stats0() {
    __shared__ float ss[CC], sq[CC];
    int t = threadIdx.x;
    if (t < CC) { ss[t] = 0.0f; sq[t] = 0.0f; }
    __syncthreads();
    int lane = t & 31;
    int warp = (blockIdx.x * 256 + t) >> 5;
    int nw = (gridDim.x * 256) >> 5;
    float2 s = make_float2(0.0f, 0.0f), q = make_float2(0.0f, 0.0f);
    for (int e = warp; e < EE; e += nw) {
        int dst = g_dst[e], src = g_src[e];
        float2 p = *(const float2*)&g_P[dst * CC + 2 * lane];
        float2 qq = *(const float2*)&g_Q[src * CC + 2 * lane];
        float y0 = p.x + qq.x, y1 = p.y + qq.y;
        s.x += y0; s.y += y1;
        q.x = fmaf(y0, y0, q.x); q.y = fmaf(y1, y1, q.y);
        if (lane == 0) atomicAdd(&g_cnt[dst], 1.0f);
    }
    atomicAdd(&ss[2 * lane], s.x);
    atomicAdd(&ss[2 * lane + 1], s.y);
    atomicAdd(&sq[2 * lane], q.x);
    atomicAdd(&sq[2 * lane + 1], q.y);
    __syncthreads();
    if (t < CC) {
        atomicAdd(&g_sum[0][t], ss[t]);
        atomicAdd(&g_sq[0][t], sq[t]);
    }
}

__global__ void k_finalize(int layer, const float* __restrict__ gam,
                           const float* __restrict__ bet) {
    int c = threadIdx.x;
    float inv = 1.0f / (float)EE;
    float m = g_sum[layer][c] * inv;
    float v = g_sq[layer][c] * inv - m * m;
    float a = gam[c] * rsqrtf(v + BN_EPS);
    g_bnA[layer][c] = a;
    g_bnB[layer][c] = bet[c] - m * a;
}

// Prologue: bf16 hi/lo split of W1, W2 (row-major [k][n]).
__global__ void k_prepW(const float* __restrict__ W1, const float* __restrict__ W2) {
    const float* W = (blockIdx.x == 0) ? W1 : W2;
    for (int idx = threadIdx.x; idx < 4096; idx += 256) {
        float x = W[idx];
        __nv_bfloat16 hi = __float2bfloat16(x);
        __nv_bfloat16 lo = __float2bfloat16(x - __bfloat162float(hi));
        g_Whi[blockIdx.x][idx] = hi;
        g_Wlo[blockIdx.x][idx] = lo;
    }
}

// ---------------- WMMA edge layer (shared by layer1 & layer2) ----------------
// mode 0: A = BN0+ReLU(P[dst]+Q[src]), B = W1, out -> g_Y,  stats -> 1
// mode 1: A = BN1+ReLU(g_Y),           B = W2, out -> outE, stats -> 2
// y = Ahi*Bhi + Alo*Bhi + Ahi*Blo (fp32 accum), error ~2^-17 relative.
__global__ void __launch_bounds__(256) k_layerT(int mode, float* __restrict__ outE) {
    extern __shared__ char smem[];
    __nv_bfloat16* A_hi = (__nv_bfloat16*)(smem + O_AHI);
    __nv_bfloat16* A_lo = (__nv_bfloat16*)(smem + O_ALO);
    __nv_bfloat16* B_hi = (__nv_bfloat16*)(smem + O_BHI);
    __nv_bfloat16* B_lo = (__nv_bfloat16*)(smem + O_BLO);
    float* stage = (float*)smem;   // reuses A region after compute
    int t = threadIdx.x;

    // copy W hi/lo into padded smem (row k -> B[k*LDB .. +64))
    {
        const uint32_t* wh = (const uint32_t*)&g_Whi[mode][0];
        const uint32_t* wl = (const uint32_t*)&g_Wlo[mode][0];
#pragma unroll
        for (int i = 0; i < 8; i++) {
            int idx2 = t + i * 256;          // pair index, 0..2047
            int k = idx2 >> 5, n2 = idx2 & 31;
            ((uint32_t*)(B_hi + k * LDB))[n2] = wh[idx2];
            ((uint32_t*)(B_lo + k * LDB))[n2] = wl[idx2];
        }
    }

    // A fill: 2 threads per edge row (32 cols each), BN+ReLU+split -> bf16 hi/lo
    int e0 = blockIdx.x * 128;
    int r = t >> 1, half = t & 1;
    int e = e0 + r;
    const float* src0;
    const float* src1 = nullptr;
    int L;
    if (mode == 0) {
        src0 = &g_P[(size_t)g_dst[e] * CC];
        src1 = &g_Q[(size_t)g_src[e] * CC];
        L = 0;
    } else {
        src0 = &g_Y[(size_t)e * CC];
        L = 1;
    }
    int cbase = half * 32;
#pragma unroll
    for (int i = 0; i < 4; i++) {
        int c = cbase + i * 8;
        float4 a0 = *(const float4*)&src0[c];
        float4 a1 = *(const float4*)&src0[c + 4];
        if (mode == 0) {
            float4 b0 = *(const float4*)&src1[c];
            float4 b1 = *(const float4*)&src1[c + 4];
            a0.x += b0.x; a0.y += b0.y; a0.z += b0.z; a0.w += b0.w;
            a1.x += b1.x; a1.y += b1.y; a1.z += b1.z; a1.w += b1.w;
        }
        float v[8] = {a0.x, a0.y, a0.z, a0.w, a1.x, a1.y, a1.z, a1.w};
        float4 A0 = *(const float4*)&g_bnA[L][c];
        float4 A1 = *(const float4*)&g_bnA[L][c + 4];
        float4 B0 = *(const float4*)&g_bnB[L][c];
        float4 B1 = *(const float4*)&g_bnB[L][c + 4];
        float bnA[8] = {A0.x, A0.y, A0.z, A0.w, A1.x, A1.y, A1.z, A1.w};
        float bnB[8] = {B0.x, B0.y, B0.z, B0.w, B1.x, B1.y, B1.z, B1.w};
        uint32_t hw[4], lw[4];
#pragma unroll
        for (int j = 0; j < 4; j++) {
            float x0 = fmaxf(fmaf(bnA[2 * j],     v[2 * j],     bnB[2 * j]),     0.0f);
            float x1 = fmaxf(fmaf(bnA[2 * j + 1], v[2 * j + 1], bnB[2 * j + 1]), 0.0f);
            __nv_bfloat16 h0 = __float2bfloat16(x0);
            __nv_bfloat16 h1 = __float2bfloat16(x1);
            __nv_bfloat16 l0 = __float2bfloat16(x0 - __bfloat162float(h0));
            __nv_bfloat16 l1 = __float2bfloat16(x1 - __bfloat162float(h1));
            hw[j] = (uint32_t)__bfloat16_as_ushort(h0) |
                    ((uint32_t)__bfloat16_as_ushort(h1) << 16);
            lw[j] = (uint32_t)__bfloat16_as_ushort(l0) |
                    ((uint32_t)__bfloat16_as_ushort(l1) << 16);
        }
        *(uint4*)&A_hi[r * LDA + c] = make_uint4(hw[0], hw[1], hw[2], hw[3]);
        *(uint4*)&A_lo[r * LDA + c] = make_uint4(lw[0], lw[1], lw[2], lw[3]);
    }
    __syncthreads();

    // WMMA: warp w -> rows [w*16, w*16+16), all 64 cols
    int w = t >> 5;
    int row0 = w * 16;
    wmma::fragment<wmma::accumulator, 16, 16, 16, float> acc[4];
#pragma unroll
    for (int j = 0; j < 4; j++) wmma::fill_fragment(acc[j], 0.0f);
#pragma unroll
    for (int k0 = 0; k0 < 64; k0 += 16) {
        wmma::fragment<wmma::matrix_a, 16, 16, 16, __nv_bfloat16, wmma::row_major> ah, al;
        wmma::load_matrix_sync(ah, A_hi + row0 * LDA + k0, LDA);
        wmma::load_matrix_sync(al, A_lo + row0 * LDA + k0, LDA);
#pragma unroll
        for (int j = 0; j < 4; j++) {
            wmma::fragment<wmma::matrix_b, 16, 16, 16, __nv_bfloat16, wmma::row_major> bh, bl;
            wmma::load_matrix_sync(bh, B_hi + k0 * LDB + j * 16, LDB);
            wmma::load_matrix_sync(bl, B_lo + k0 * LDB + j * 16, LDB);
            wmma::mma_sync(acc[j], ah, bh, acc[j]);
            wmma::mma_sync(acc[j], al, bh, acc[j]);
            wmma::mma_sync(acc[j], ah, bl, acc[j]);
        }
    }
    __syncthreads();   // everyone done reading A region before stage overwrite
#pragma unroll
    for (int j = 0; j < 4; j++)
        wmma::store_matrix_sync(stage + row0 * LDS_F + j * 16, acc[j], LDS_F,
                                wmma::mem_row_major);
    __syncthreads();

    // column stats: 256 threads, c = t&63, quarter sums 32 rows
    {
        int c = t & 63, quarter = t >> 6;
        float s = 0.0f, q = 0.0f;
#pragma unroll 8
        for (int rr = 0; rr < 32; rr++) {
            float vv = stage[(quarter * 32 + rr) * LDS_F + c];
            s += vv;
            q = fmaf(vv, vv, q);
        }
        int SL = (mode == 0) ? 1 : 2;
        atomicAdd(&g_sum[SL][c], s);
        atomicAdd(&g_sq[SL][c], q);
    }

    // coalesced store of the 128x64 tile
    float* dst = (mode == 0) ? (g_Y + (size_t)e0 * CC) : (outE + (size_t)e0 * CC);
#pragma unroll
    for (int j2 = 0; j2 < 8; j2++) {
        int f = j2 * 1024 + t * 4;
        int rr = f >> 6, cc2 = f & 63;
        uint4 v = *(const uint4*)&stage[rr * LDS_F + cc2];
        *(uint4*)&dst[f] = v;
    }
}

// BN2 + ReLU in place, vector red.v4 scatter into node sums.
__global__ void k_scatter(float* __restrict__ out) {
    int i = blockIdx.x * 256 + threadIdx.x;
    if (i >= EE * 4) return;
    int e = i >> 2, q = i & 3;
    float* oe = out + (size_t)NN * CC + (size_t)e * CC + q * 16;
    int dst = g_dst[e];
    float* a = out + (size_t)dst * CC + q * 16;
#pragma unroll
    for (int j = 0; j < 4; j++) {
        float4 v = *(float4*)&oe[j * 4];
        float4 A = *(const float4*)&g_bnA[2][q * 16 + j * 4];
        float4 B = *(const float4*)&g_bnB[2][q * 16 + j * 4];
        v.x = fmaxf(fmaf(A.x, v.x, B.x), 0.0f);
        v.y = fmaxf(fmaf(A.y, v.y, B.y), 0.0f);
        v.z = fmaxf(fmaf(A.z, v.z, B.z), 0.0f);
        v.w = fmaxf(fmaf(A.w, v.w, B.w), 0.0f);
        *(float4*)&oe[j * 4] = v;
        asm volatile("red.global.add.v4.f32 [%0], {%1, %2, %3, %4};"
                     :: "l"(a + j * 4), "f"(v.x), "f"(v.y), "f"(v.z), "f"(v.w)
                     : "memory");
    }
}

__global__ void k_div(float* __restrict__ out) {
    int i = blockIdx.x * 256 + threadIdx.x;
    if (i < NN * CC) {
        float c = g_cnt[i >> 6];
        out[i] = out[i] / fmaxf(c, 1.0f);
    }
}

extern "C" void kernel_launch(void* const* d_in, const int* in_sizes, int n_in,
                              void* d_out, int out_size) {
    const float* x = (const float*)d_in[0];
    const void* ei = d_in[1];
    const float* W0 = (const float*)d_in[2];
    const float* g0 = (const float*)d_in[4];
    const float* be0 = (const float*)d_in[5];
    const float* W1 = (const float*)d_in[6];
    const float* g1 = (const float*)d_in[8];
    const float* be1 = (const float*)d_in[9];
    const float* W2 = (const float*)d_in[10];
    const float* g2 = (const float*)d_in[12];
    const float* be2 = (const float*)d_in[13];
    float* out = (float*)d_out;
    float* outE = out + NN * CC;

    static int s_attr_done = 0;
    if (!s_attr_done) {
        cudaFuncSetAttribute(k_layerT, cudaFuncAttributeMaxDynamicSharedMemorySize, SMEM_LK);
        s_attr_done = 1;
    }

    k_zero<<<(NN * CC + 255) / 256, 256>>>(out);
    k_detect<<<1, 256>>>((const unsigned*)ei);
    k_convert<<<(EE + 255) / 256, 256>>>(ei);
    k_prepW<<<2, 256>>>(W1, W2);
    k_node<<<(NN + 31) / 32, 256>>>(x, W0);
    k_stats0<<<2048, 256>>>();
    k_finalize<<<1, 64>>>(0, g0, be0);
    k_layerT<<<EE / 128, 256, SMEM_LK>>>(0, outE);
    k_finalize<<<1, 64>>>(1, g1, be1);
    k_layerT<<<EE / 128, 256, SMEM_LK>>>(1, outE);
    k_finalize<<<1, 64>>>(2, g2, be2);
    k_scatter<<<(EE * 4 + 255) / 256, 256>>>(out);
    k_div<<<(NN * CC + 255) / 256, 256>>>(out);
}